// round 4
// baseline (speedup 1.0000x reference)
#include <cuda_runtime.h>

// Problem constants (fixed by the dataset)
#define BB     16384   // batch
#define TT     60
#define II     32      // input / output feature dim
#define HH     128     // hidden dim
#define STEPS  30
#define SEQOFF 30      // x[:, 30, :] is the only x slice used

#define MT   32        // batch elements per CTA
#define NTH  256       // threads per CTA

typedef unsigned long long u64;

// ---------------------------------------------------------------------------
// Packed (transposed) weights in device-global scratch. Repacked every launch.
//   g_Wx[k][g]  = W_ih[g][k]   k in [0,32),  g in [0,384)
//   g_Wh[k][g]  = W_hh[g][k]   k in [0,128), g in [0,384)
//   g_Wot[k][i] = W_out[i][k]  k in [0,128), i in [0,32)
// ---------------------------------------------------------------------------
__device__ __align__(16) float g_Wx[32 * 384];
__device__ __align__(16) float g_Wh[128 * 384];
__device__ __align__(16) float g_Wot[128 * 32];
__device__ float g_br[128], g_bz[128], g_bin[128], g_bhn[128];

__global__ void pack_kernel(const float* __restrict__ W_ih,
                            const float* __restrict__ W_hh,
                            const float* __restrict__ W_out,
                            const float* __restrict__ b_ih,
                            const float* __restrict__ b_hh)
{
    int idx = blockIdx.x * blockDim.x + threadIdx.x;
    if (idx < 12288) {                       // Wx: 32*384
        int k = idx / 384, g = idx - k * 384;
        g_Wx[idx] = W_ih[g * 32 + k];
    }
    int i2 = idx - 12288;                    // Wh: 128*384
    if (i2 >= 0 && i2 < 49152) {
        int k = i2 / 384, g = i2 - k * 384;
        g_Wh[i2] = W_hh[g * 128 + k];
    }
    int i3 = idx - 61440;                    // Wot: 128*32
    if (i3 >= 0 && i3 < 4096) {
        int k = i3 >> 5, i = i3 & 31;
        g_Wot[i3] = W_out[i * 128 + k];
    }
    int i4 = idx - 65536;                    // biases
    if (i4 >= 0 && i4 < 128) {
        g_br[i4]  = b_ih[i4]        + b_hh[i4];
        g_bz[i4]  = b_ih[128 + i4]  + b_hh[128 + i4];
        g_bin[i4] = b_ih[256 + i4];
        g_bhn[i4] = b_hh[256 + i4];
    }
}

// ---------------------------------------------------------------------------
// Packed f32x2 helpers (FFMA2 — only reachable via PTX on sm_103a)
// ---------------------------------------------------------------------------
__device__ __forceinline__ u64 dup2(float v) {
    u64 r; asm("mov.b64 %0, {%1, %1};" : "=l"(r) : "f"(v)); return r;
}
__device__ __forceinline__ void unpack2(u64 v, float& lo, float& hi) {
    asm("mov.b64 {%0, %1}, %2;" : "=f"(lo), "=f"(hi) : "l"(v));
}
__device__ __forceinline__ u64 fma2(u64 a, u64 b, u64 c) {
    u64 d; asm("fma.rn.f32x2 %0, %1, %2, %3;" : "=l"(d) : "l"(a), "l"(b), "l"(c));
    return d;
}

__device__ __forceinline__ float sigmoid_f(float v) {
    return __fdividef(1.0f, 1.0f + __expf(-v));
}
__device__ __forceinline__ float tanh_f(float v) {
    // 1 - 2/(e^{2v}+1): exact saturation at +/-1, ~2^-21 rel err otherwise
    return 1.0f - __fdividef(2.0f, __expf(2.0f * v) + 1.0f);
}

// ---------------------------------------------------------------------------
// Main recurrent kernel. One CTA = 32 batch elements for all 30 steps.
// Activation state transposed in smem: A[buf][k][m], k in [0,160)
// (rows 0..31 = x_t, rows 32..159 = h_t), row stride 36 floats.
// Thread tile: 4 batch (m) x 4 hidden (j); j-pairs packed into f32x2.
// ---------------------------------------------------------------------------
__global__ __launch_bounds__(NTH, 2)
void gru_kernel(const float* __restrict__ x,
                const float* __restrict__ h0,
                const float* __restrict__ b_out,
                float* __restrict__ out)
{
    __shared__ float A[2][160][36];

    const int tid = threadIdx.x;
    const int b0  = blockIdx.x * MT;
    const int tm4 = (tid >> 5) << 2;   // batch offset within tile: 0,4,...,28
    const int tj  = tid & 31;          // lane: j-group / output feature
    const int j4  = tj << 2;           // hidden offset: 0,4,...,124

    // ---- prologue: x0 = x[:,30,:]  and  h0 into A[0] (transposed) ----
    for (int idx = tid; idx < MT * II; idx += NTH) {
        int m = idx >> 5, i = idx & 31;
        A[0][i][m] = x[(size_t)(b0 + m) * (TT * II) + SEQOFF * II + i];
    }
    for (int idx = tid; idx < MT * HH; idx += NTH) {
        int m = idx >> 7, k = idx & 127;
        A[0][32 + k][m] = h0[(size_t)(b0 + m) * HH + k];
    }

    float br_[4], bz_[4], bin_[4], bhn_[4];
#pragma unroll
    for (int ji = 0; ji < 4; ji++) {
        br_[ji]  = g_br[j4 + ji];
        bz_[ji]  = g_bz[j4 + ji];
        bin_[ji] = g_bin[j4 + ji];
        bhn_[ji] = g_bhn[j4 + ji];
    }
    const float bo = b_out[tj];
    __syncthreads();

    for (int t = 0; t < STEPS; t++) {
        const int cur = t & 1, nxt = cur ^ 1;

        // Accumulators: [mi][jpair], each u64 = two f32 lanes (j even/odd)
        u64 ar2[4][2], az2[4][2], ain2[4][2], ahn2[4][2];
#pragma unroll
        for (int mi = 0; mi < 4; mi++)
#pragma unroll
            for (int jp = 0; jp < 2; jp++) {
                ar2[mi][jp] = 0ULL; az2[mi][jp] = 0ULL;
                ain2[mi][jp] = 0ULL; ahn2[mi][jp] = 0ULL;
            }

        // ---- gate GEMM, x part (K = 32): accumulates r, z, i_n ----
#pragma unroll 2
        for (int k = 0; k < II; k++) {
            const float4 a = *(const float4*)&A[cur][k][tm4];   // warp-uniform
            const u64 amd[4] = {dup2(a.x), dup2(a.y), dup2(a.z), dup2(a.w)};
            const ulonglong2 wr = __ldg((const ulonglong2*)&g_Wx[k * 384 + j4]);
            const ulonglong2 wz = __ldg((const ulonglong2*)&g_Wx[k * 384 + 128 + j4]);
            const ulonglong2 wn = __ldg((const ulonglong2*)&g_Wx[k * 384 + 256 + j4]);
#pragma unroll
            for (int mi = 0; mi < 4; mi++) {
                ar2[mi][0]  = fma2(amd[mi], wr.x, ar2[mi][0]);
                ar2[mi][1]  = fma2(amd[mi], wr.y, ar2[mi][1]);
                az2[mi][0]  = fma2(amd[mi], wz.x, az2[mi][0]);
                az2[mi][1]  = fma2(amd[mi], wz.y, az2[mi][1]);
                ain2[mi][0] = fma2(amd[mi], wn.x, ain2[mi][0]);
                ain2[mi][1] = fma2(amd[mi], wn.y, ain2[mi][1]);
            }
        }

        // ---- gate GEMM, h part (K = 128): accumulates r, z, h_n ----
#pragma unroll 2
        for (int k = 0; k < HH; k++) {
            const float4 a = *(const float4*)&A[cur][32 + k][tm4];
            const u64 amd[4] = {dup2(a.x), dup2(a.y), dup2(a.z), dup2(a.w)};
            const ulonglong2 wr = __ldg((const ulonglong2*)&g_Wh[k * 384 + j4]);
            const ulonglong2 wz = __ldg((const ulonglong2*)&g_Wh[k * 384 + 128 + j4]);
            const ulonglong2 wn = __ldg((const ulonglong2*)&g_Wh[k * 384 + 256 + j4]);
#pragma unroll
            for (int mi = 0; mi < 4; mi++) {
                ar2[mi][0]  = fma2(amd[mi], wr.x, ar2[mi][0]);
                ar2[mi][1]  = fma2(amd[mi], wr.y, ar2[mi][1]);
                az2[mi][0]  = fma2(amd[mi], wz.x, az2[mi][0]);
                az2[mi][1]  = fma2(amd[mi], wz.y, az2[mi][1]);
                ahn2[mi][0] = fma2(amd[mi], wn.x, ahn2[mi][0]);
                ahn2[mi][1] = fma2(amd[mi], wn.y, ahn2[mi][1]);
            }
        }

        // ---- activations + h_new -> A[nxt] hidden rows ----
#pragma unroll
        for (int jp = 0; jp < 2; jp++) {
            const int j0 = j4 + 2 * jp;
            const float4 he = *(const float4*)&A[cur][32 + j0][tm4];
            const float4 hoq = *(const float4*)&A[cur][32 + j0 + 1][tm4];
            const float he_[4] = {he.x, he.y, he.z, he.w};
            const float ho_[4] = {hoq.x, hoq.y, hoq.z, hoq.w};
            float hn0[4], hn1[4];
#pragma unroll
            for (int mi = 0; mi < 4; mi++) {
                float vr0, vr1, vz0, vz1, vi0, vi1, vh0, vh1;
                unpack2(ar2[mi][jp], vr0, vr1);
                unpack2(az2[mi][jp], vz0, vz1);
                unpack2(ain2[mi][jp], vi0, vi1);
                unpack2(ahn2[mi][jp], vh0, vh1);
                {   // j = j0 (even lane)
                    const int ji = 2 * jp;
                    float r = sigmoid_f(vr0 + br_[ji]);
                    float z = sigmoid_f(vz0 + bz_[ji]);
                    float n = tanh_f(fmaf(r, vh0 + bhn_[ji], vi0 + bin_[ji]));
                    hn0[mi] = n + z * (he_[mi] - n);
                }
                {   // j = j0+1 (odd lane)
                    const int ji = 2 * jp + 1;
                    float r = sigmoid_f(vr1 + br_[ji]);
                    float z = sigmoid_f(vz1 + bz_[ji]);
                    float n = tanh_f(fmaf(r, vh1 + bhn_[ji], vi1 + bin_[ji]));
                    hn1[mi] = n + z * (ho_[mi] - n);
                }
            }
            *(float4*)&A[nxt][32 + j0][tm4] =
                make_float4(hn0[0], hn0[1], hn0[2], hn0[3]);
            *(float4*)&A[nxt][32 + j0 + 1][tm4] =
                make_float4(hn1[0], hn1[1], hn1[2], hn1[3]);
        }
        __syncthreads();   // Hnew complete

        // ---- output GEMM: y = h_new @ W_out^T + b_out (lane = feature i) ----
        // Packed over batch pairs: (m0,m1) and (m2,m3) are natural smem pairs.
        u64 y01 = dup2(bo), y23 = dup2(bo);
#pragma unroll 4
        for (int k = 0; k < HH; k++) {
            const ulonglong2 hv = *(const ulonglong2*)&A[nxt][32 + k][tm4];
            const u64 wd = dup2(__ldg(&g_Wot[(k << 5) + tj]));
            y01 = fma2(hv.x, wd, y01);
            y23 = fma2(hv.y, wd, y23);
        }
        float yv[4];
        unpack2(y01, yv[0], yv[1]);
        unpack2(y23, yv[2], yv[3]);
#pragma unroll
        for (int mi = 0; mi < 4; mi++) {
            out[((size_t)(b0 + tm4 + mi) * STEPS + t) * II + tj] = yv[mi];
            A[nxt][tj][tm4 + mi] = yv[mi];   // y feeds back as x_{t+1}
        }
        __syncthreads();   // x rows of A[nxt] complete before next step
    }
}

// ---------------------------------------------------------------------------
// Harness entry point
// ---------------------------------------------------------------------------
extern "C" void kernel_launch(void* const* d_in, const int* in_sizes, int n_in,
                              void* d_out, int out_size)
{
    const float* x     = (const float*)d_in[0];
    const float* h     = (const float*)d_in[1];
    const float* W_ih  = (const float*)d_in[2];
    const float* W_hh  = (const float*)d_in[3];
    const float* b_ih  = (const float*)d_in[4];
    const float* b_hh  = (const float*)d_in[5];
    const float* W_out = (const float*)d_in[6];
    const float* b_out = (const float*)d_in[7];
    float* out = (float*)d_out;

    pack_kernel<<<257, 256>>>(W_ih, W_hh, W_out, b_ih, b_hh);
    gru_kernel<<<BB / MT, NTH>>>(x, h, b_out, out);
}